// round 1
// baseline (speedup 1.0000x reference)
#include <cuda_runtime.h>

// ActiveParticles step, N=4096.
// Inputs (metadata order): positions[N,2] f32, orientations[N,2] f32,
// Deltas[1] f32, rot_noise[N] f32, trans_noise[N,2] f32.
// Output: [5, N, 2] f32 = {new_p, new_u, orientation_sums, leftturns, rightturns}.

#define NMAX 4096

static __device__ float2 g_cms;
static __device__ float2 g_bufA[NMAX];
static __device__ float2 g_bufB[NMAX];

__device__ __forceinline__ float wsum(float v) {
#pragma unroll
    for (int o = 16; o; o >>= 1) v += __shfl_xor_sync(0xffffffffu, v, o);
    return v;
}

__device__ __forceinline__ float anglewrap(float diff) {
    const float PI_F = 3.1415927410125732f;
    if (diff <= -PI_F) diff = diff - PI_F * floorf(diff / PI_F);  // jnp.mod(diff, PI)
    if (diff >= PI_F) diff -= 2.0f * PI_F;
    return diff;
}

__device__ __forceinline__ float anglediff(float ax, float ay, float bx, float by) {
    return anglewrap(atan2f(ay, ax) - atan2f(by, bx));
}

// ---------------- kernel 0: cms = mean(p) (mask_ra is identically all-true) --------
__global__ void mean_kernel(const float* __restrict__ pos_, int n) {
    __shared__ float2 sh[32];
    const float2* p = (const float2*)pos_;
    float sx = 0.f, sy = 0.f;
    for (int j = threadIdx.x; j < n; j += blockDim.x) {
        float2 v = p[j];
        sx += v.x; sy += v.y;
    }
    sx = wsum(sx); sy = wsum(sy);
    int lane = threadIdx.x & 31, w = threadIdx.x >> 5;
    if (lane == 0) sh[w] = make_float2(sx, sy);
    __syncthreads();
    if (w == 0) {
        int nw = blockDim.x >> 5;
        float2 v = (lane < nw) ? sh[lane] : make_float2(0.f, 0.f);
        float ax = wsum(v.x), ay = wsum(v.y);
        if (lane == 0) {
            float inv = 1.0f / fmaxf((float)n, 1.0f);   // max(n_a, 1) with n_a = n
            g_cms = make_float2(ax * inv, ay * inv);
        }
    }
}

// ---------------- kernel 1: main pairwise pass, one warp per particle --------------
__global__ void main_kernel(const float* __restrict__ pos_, const float* __restrict__ ori_,
                            const float* __restrict__ deltas, const float* __restrict__ rnoise,
                            const float* __restrict__ tnoise_, float* __restrict__ out, int n) {
    const float2* p = (const float2*)pos_;
    const float2* u = (const float2*)ori_;
    const float2* tn = (const float2*)tnoise_;

    int wid = (int)((blockIdx.x * blockDim.x + threadIdx.x) >> 5);
    int lane = threadIdx.x & 31;
    if (wid >= n) return;
    const int i = wid;

    const float2 pi = __ldg(&p[i]);
    const float2 ui = __ldg(&u[i]);

    const float RRf  = (float)8e-6;                       // RR
    const float RR2  = RRf * RRf;
    const float ROCf = (float)(2.5e-5 + 3.15e-6);         // RO + RC
    const float ROC2 = ROCf * ROCf;

    float nr = 0.f, srx = 0.f, sry = 0.f, osx = 0.f, osy = 0.f;

    for (int j = lane; j < n; j += 32) {
        float2 pj = __ldg(&p[j]);
        float2 uj = __ldg(&u[j]);
        float dx = pj.x - pi.x, dy = pj.y - pi.y;
        float d2 = dx * dx + dy * dy;
        if (d2 <= ROC2) {            // mask_ro (within_view identically true; includes j==i)
            osx += uj.x; osy += uj.y;
        }
        if (d2 <= RR2 && j != i) {   // inside_Rr
            // in_front: wrap(angle(dir)-angle(u_j)) < pi/2  <=>  !(dot<=0 && cross>=0)
            float c = dx * uj.x + dy * uj.y;
            float s = uj.x * dy - uj.y * dx;
            if (!(c <= 0.0f && s >= 0.0f)) {
                nr += 1.0f; srx += pj.x; sry += pj.y;
            }
        }
    }
    nr = wsum(nr); srx = wsum(srx); sry = wsum(sry); osx = wsum(osx); osy = wsum(osy);

    // ---- per-particle epilogue (all lanes redundant, lane 0 writes) ----
    float sgn = (nr > 0.f) ? 1.0f : 0.0f;
    float invr = 1.0f / fmaxf(nr, 1.0f);
    float Sx = srx * invr - pi.x * sgn;
    float Sy = sry * invr - pi.y * sgn;
    float dax = -Sx, day = -Sy;

    float2 cms = g_cms;
    float Psx = cms.x - pi.x;            // sign(n_a) == 1
    float Psy = cms.y - pi.y;

    float Delta = __ldg(&deltas[0]);
    float cd = cosf(Delta), sd = sinf(Delta);
    float lx = Psx * cd - Psy * sd, ly = Psx * sd + Psy * cd;   // Ps * e^{+i D}
    float rx = Psx * cd + Psy * sd, ry = Psy * cd - Psx * sd;   // Ps * e^{-i D}

    const float EPSF = 1e-14f;
    float nb  = fmaxf(sqrtf(osx * osx + osy * osy + 1e-30f), EPSF);
    float naL = fmaxf(sqrtf(lx * lx + ly * ly + 1e-30f), EPSF);
    float naR = fmaxf(sqrtf(rx * rx + ry * ry + 1e-30f), EPSF);
    float csL = (lx * osx + ly * osy) / (naL * nb);
    float csR = (rx * osx + ry * osy) / (naR * nb);
    bool left_closer = (csL >= csR);
    float bx = left_closer ? lx : rx;
    float by = left_closer ? ly : ry;

    float d_abs = sqrtf(dax * dax + day * day);
    float ang;
    if (d_abs > 0.f) {
        ang = anglediff(dax, day, ui.x, ui.y);
    } else {
        float babs = sqrtf(bx * bx + by * by);
        float bsx = (babs > 0.f) ? bx : 1.0f;
        float bsy = (babs > 0.f) ? by : 0.0f;
        ang = anglediff(bsx, bsy, ui.x, ui.y);
    }

    const float C1   = (float)(0.2 * 25.0 * 0.0028);      // dt*Gamma*DR
    const float S2DR = (float)0.07483314773547883;        // sqrt(2*DR)
    const float SDT  = (float)0.4472135954999579;         // sqrt(dt)
    float phi = C1 * sinf(ang) + rnoise[i] * S2DR * SDT;
    float cr = cosf(phi), sr = sinf(phi);
    float nux = ui.x * cr - ui.y * sr;
    float nuy = ui.x * sr + ui.y * cr;

    const float DTV  = (float)(0.2 * 5e-7);               // dt*velocity
    const float CSH  = (float)0.7071067811865476;         // sqrt(0.5)
    const float C2T  = (float)1.6733200530681511e-07;     // sqrt(2*DT_trans)
    float2 t = __ldg(&tn[i]);
    float tx = DTV * ui.x + ((t.x * CSH) * C2T) * SDT;
    float ty = DTV * ui.y + ((t.y * CSH) * C2T) * SDT;

    if (lane == 0) {
        g_bufA[i] = make_float2(pi.x + tx, pi.y + ty);    // pos before collisions
        int b = 2 * n;
        out[1 * b + 2 * i + 0] = nux;  out[1 * b + 2 * i + 1] = nuy;
        out[2 * b + 2 * i + 0] = osx;  out[2 * b + 2 * i + 1] = osy;
        out[3 * b + 2 * i + 0] = lx;   out[3 * b + 2 * i + 1] = ly;
        out[4 * b + 2 * i + 0] = rx;   out[4 * b + 2 * i + 1] = ry;
    }
}

// ---------------- kernels 2-4: collision sweep, one warp per particle --------------
// pass 0: A->B, pass 1: B->A, pass 2: A->out_final
__global__ void collide_kernel(int pass, float2* __restrict__ out_final, int n) {
    const float2* src = (pass == 1) ? g_bufB : g_bufA;
    float2* dst = (pass == 0) ? g_bufB : (pass == 1) ? g_bufA : out_final;

    int wid = (int)((blockIdx.x * blockDim.x + threadIdx.x) >> 5);
    int lane = threadIdx.x & 31;
    if (wid >= n) return;
    const int i = wid;

    const float2 pi = __ldg(&src[i]);
    const float TH  = (float)(2.0 * 3.15e-6);    // 2*RC
    const float TH2 = TH * TH;
    const float C21 = (float)(2.1 * 3.15e-6);    // 2.1*RC

    float mvx = 0.f, mvy = 0.f;
    for (int j = lane; j < n; j += 32) {
        float2 pj = __ldg(&src[j]);
        float dx = pj.x - pi.x, dy = pj.y - pi.y;
        float d2 = dx * dx + dy * dy;
        if (d2 <= TH2 && j != i) {
            float ab = sqrtf(d2);
            float sc = (C21 - ab) * 0.5f / ab;
            mvx += dx * sc; mvy += dy * sc;
        }
    }
    mvx = wsum(mvx); mvy = wsum(mvy);
    if (lane == 0) dst[i] = make_float2(pi.x - mvx, pi.y - mvy);
}

extern "C" void kernel_launch(void* const* d_in, const int* in_sizes, int n_in,
                              void* d_out, int out_size) {
    const float* pos = (const float*)d_in[0];
    const float* ori = (const float*)d_in[1];
    const float* del = (const float*)d_in[2];
    const float* rno = (const float*)d_in[3];
    const float* tno = (const float*)d_in[4];
    float* out = (float*)d_out;
    const int n = in_sizes[3];                   // rot_noise has N elements

    const int threads = 256;
    const int blocks = (n * 32 + threads - 1) / threads;   // one warp per particle

    mean_kernel<<<1, 1024>>>(pos, n);
    main_kernel<<<blocks, threads>>>(pos, ori, del, rno, tno, out, n);
    collide_kernel<<<blocks, threads>>>(0, nullptr, n);
    collide_kernel<<<blocks, threads>>>(1, nullptr, n);
    collide_kernel<<<blocks, threads>>>(2, (float2*)out, n);  // writes new_p block
}

// round 2
// speedup vs baseline: 2.3878x; 2.3878x over previous
#include <cuda_runtime.h>

// ActiveParticles step, N=4096.
// Inputs: positions[N,2] f32, orientations[N,2] f32, Deltas[1] f32,
//         rot_noise[N] f32, trans_noise[N,2] f32.
// Output: [5, N, 2] f32 = {new_p, new_u, orientation_sums, leftturns, rightturns}.

#define NMAX 4096

static __device__ float2 g_cms;
static __device__ float4 g_pu[NMAX];            // (p.x, p.y, u.x, u.y)
static __device__ float4 g_posA4[NMAX / 2];     // positions ping
static __device__ float4 g_posB4[NMAX / 2];     // positions pong

__device__ __forceinline__ float wsum(float v) {
#pragma unroll
    for (int o = 16; o; o >>= 1) v += __shfl_xor_sync(0xffffffffu, v, o);
    return v;
}

__device__ __forceinline__ float anglewrap(float diff) {
    const float PI_F = 3.1415927410125732f;
    if (diff <= -PI_F) diff = diff - PI_F * floorf(diff / PI_F);  // jnp.mod(diff, PI)
    if (diff >= PI_F) diff -= 2.0f * PI_F;
    return diff;
}

__device__ __forceinline__ float anglediff(float ax, float ay, float bx, float by) {
    return anglewrap(atan2f(ay, ax) - atan2f(by, bx));
}

// ---------------- kernel P: pack (p,u) into float4 -------------------------------
__global__ void pack_kernel(const float2* __restrict__ p, const float2* __restrict__ u, int n) {
    int i = blockIdx.x * blockDim.x + threadIdx.x;
    if (i < n) {
        float2 pp = p[i], uu = u[i];
        g_pu[i] = make_float4(pp.x, pp.y, uu.x, uu.y);
    }
}

// ---------------- kernel 0: cms = mean(p) (mask_ra identically all-true) ----------
__global__ void mean_kernel(const float* __restrict__ pos_, int n) {
    __shared__ float2 sh[32];
    const float2* p = (const float2*)pos_;
    float sx = 0.f, sy = 0.f;
    for (int j = threadIdx.x; j < n; j += blockDim.x) {
        float2 v = p[j];
        sx += v.x; sy += v.y;
    }
    sx = wsum(sx); sy = wsum(sy);
    int lane = threadIdx.x & 31, w = threadIdx.x >> 5;
    if (lane == 0) sh[w] = make_float2(sx, sy);
    __syncthreads();
    if (w == 0) {
        int nw = blockDim.x >> 5;
        float2 v = (lane < nw) ? sh[lane] : make_float2(0.f, 0.f);
        float ax = wsum(v.x), ay = wsum(v.y);
        if (lane == 0) {
            float inv = 1.0f / fmaxf((float)n, 1.0f);
            g_cms = make_float2(ax * inv, ay * inv);
        }
    }
}

// ---------------- kernel 1: main pairwise pass, one warp per particle --------------
__global__ void __launch_bounds__(256) main_kernel(
        const float* __restrict__ pos_, const float* __restrict__ ori_,
        const float* __restrict__ deltas, const float* __restrict__ rnoise,
        const float* __restrict__ tnoise_, float* __restrict__ out, int n) {
    const float2* tn = (const float2*)tnoise_;

    int wid = (int)((blockIdx.x * blockDim.x + threadIdx.x) >> 5);
    int lane = threadIdx.x & 31;
    if (wid >= n) return;
    const int i = wid;

    const float4 me = g_pu[i];
    const float pix = me.x, piy = me.y, uix = me.z, uiy = me.w;

    const float RRf  = (float)8e-6;
    const float RR2  = RRf * RRf;
    const float ROCf = (float)(2.5e-5 + 3.15e-6);
    const float ROC2 = ROCf * ROCf;

    float nr = 0.f, srx = 0.f, sry = 0.f, osx = 0.f, osy = 0.f;

    // n is a multiple of 128 (N=4096): 4 float4 loads per lane per iteration.
    for (int base = 0; base < n; base += 128) {
        float4 a0 = g_pu[base + lane];
        float4 a1 = g_pu[base + lane + 32];
        float4 a2 = g_pu[base + lane + 64];
        float4 a3 = g_pu[base + lane + 96];
#pragma unroll
        for (int k = 0; k < 4; k++) {
            float4 a = (k == 0) ? a0 : (k == 1) ? a1 : (k == 2) ? a2 : a3;
            int j = base + lane + 32 * k;
            float dx = a.x - pix, dy = a.y - piy;
            float d2 = dx * dx + dy * dy;
            if (d2 <= ROC2) { osx += a.z; osy += a.w; }   // mask_ro (incl. j==i)
            if (d2 <= RR2 && j != i) {
                // in_front: wrap(angle(dir)-angle(u_j)) < pi/2 <=> !(dot<=0 && cross>=0)
                float c = dx * a.z + dy * a.w;
                float s = a.z * dy - a.w * dx;
                if (!(c <= 0.0f && s >= 0.0f)) { nr += 1.0f; srx += a.x; sry += a.y; }
            }
        }
    }
    nr = wsum(nr); srx = wsum(srx); sry = wsum(sry); osx = wsum(osx); osy = wsum(osy);

    // ---- per-particle epilogue ----
    float sgn = (nr > 0.f) ? 1.0f : 0.0f;
    float invr = 1.0f / fmaxf(nr, 1.0f);
    float Sx = srx * invr - pix * sgn;
    float Sy = sry * invr - piy * sgn;
    float dax = -Sx, day = -Sy;

    float2 cms = g_cms;
    float Psx = cms.x - pix;   // sign(n_a) == 1
    float Psy = cms.y - piy;

    float Delta = __ldg(&deltas[0]);
    float cd = cosf(Delta), sd = sinf(Delta);
    float lx = Psx * cd - Psy * sd, ly = Psx * sd + Psy * cd;   // Ps * e^{+iD}
    float rx = Psx * cd + Psy * sd, ry = Psy * cd - Psx * sd;   // Ps * e^{-iD}

    const float EPSF = 1e-14f;
    float nb  = fmaxf(sqrtf(osx * osx + osy * osy + 1e-30f), EPSF);
    float naL = fmaxf(sqrtf(lx * lx + ly * ly + 1e-30f), EPSF);
    float naR = fmaxf(sqrtf(rx * rx + ry * ry + 1e-30f), EPSF);
    float csL = (lx * osx + ly * osy) / (naL * nb);
    float csR = (rx * osx + ry * osy) / (naR * nb);
    bool left_closer = (csL >= csR);
    float bx = left_closer ? lx : rx;
    float by = left_closer ? ly : ry;

    float d_abs = sqrtf(dax * dax + day * day);
    float ang;
    if (d_abs > 0.f) {
        ang = anglediff(dax, day, uix, uiy);
    } else {
        float babs = sqrtf(bx * bx + by * by);
        float bsx = (babs > 0.f) ? bx : 1.0f;
        float bsy = (babs > 0.f) ? by : 0.0f;
        ang = anglediff(bsx, bsy, uix, uiy);
    }

    const float C1   = (float)(0.2 * 25.0 * 0.0028);
    const float S2DR = (float)0.07483314773547883;     // sqrt(2*DR)
    const float SDT  = (float)0.4472135954999579;      // sqrt(dt)
    float phi = C1 * sinf(ang) + rnoise[i] * S2DR * SDT;
    float cr = cosf(phi), sr = sinf(phi);
    float nux = uix * cr - uiy * sr;
    float nuy = uix * sr + uiy * cr;

    const float DTV = (float)(0.2 * 5e-7);
    const float CSH = (float)0.7071067811865476;       // sqrt(0.5)
    const float C2T = (float)1.6733200530681511e-07;   // sqrt(2*DT_trans)
    float2 t = __ldg(&tn[i]);
    float tx = DTV * uix + ((t.x * CSH) * C2T) * SDT;
    float ty = DTV * uiy + ((t.y * CSH) * C2T) * SDT;

    if (lane == 0) {
        ((float2*)g_posA4)[i] = make_float2(pix + tx, piy + ty);
        int b = 2 * n;
        out[1 * b + 2 * i + 0] = nux;  out[1 * b + 2 * i + 1] = nuy;
        out[2 * b + 2 * i + 0] = osx;  out[2 * b + 2 * i + 1] = osy;
        out[3 * b + 2 * i + 0] = lx;   out[3 * b + 2 * i + 1] = ly;
        out[4 * b + 2 * i + 0] = rx;   out[4 * b + 2 * i + 1] = ry;
    }
}

// ---------------- kernels 2-4: collision sweep, one warp per particle --------------
// pass 0: A->B, pass 1: B->A, pass 2: A->out_final
__global__ void __launch_bounds__(256) collide_kernel(int pass, float2* __restrict__ out_final, int n) {
    const float4* src4 = (pass == 1) ? g_posB4 : g_posA4;
    float2* dst = (pass == 0) ? (float2*)g_posB4 : (pass == 1) ? (float2*)g_posA4 : out_final;

    int wid = (int)((blockIdx.x * blockDim.x + threadIdx.x) >> 5);
    int lane = threadIdx.x & 31;
    if (wid >= n) return;
    const int i = wid;

    const float2 pi = ((const float2*)src4)[i];
    const float TH  = (float)(2.0 * 3.15e-6);     // 2*RC
    const float TH2 = TH * TH;
    const float C21 = (float)(2.1 * 3.15e-6);     // 2.1*RC

    float mvx = 0.f, mvy = 0.f;
    // n multiple of 256: 4 float4 (=8 particles) per lane per iteration.
    for (int base = 0; base < n; base += 256) {
        int q = (base >> 1) + lane;
        float4 q0 = src4[q];
        float4 q1 = src4[q + 32];
        float4 q2 = src4[q + 64];
        float4 q3 = src4[q + 96];
#pragma unroll
        for (int k = 0; k < 4; k++) {
            float4 v = (k == 0) ? q0 : (k == 1) ? q1 : (k == 2) ? q2 : q3;
            int j0 = base + 2 * (lane + 32 * k);
            {
                float dx = v.x - pi.x, dy = v.y - pi.y;
                float d2 = dx * dx + dy * dy;
                if (d2 <= TH2 && j0 != i) {
                    float ab = sqrtf(d2);
                    float sc = (C21 - ab) * 0.5f / ab;
                    mvx += dx * sc; mvy += dy * sc;
                }
            }
            {
                float dx = v.z - pi.x, dy = v.w - pi.y;
                float d2 = dx * dx + dy * dy;
                if (d2 <= TH2 && (j0 + 1) != i) {
                    float ab = sqrtf(d2);
                    float sc = (C21 - ab) * 0.5f / ab;
                    mvx += dx * sc; mvy += dy * sc;
                }
            }
        }
    }
    mvx = wsum(mvx); mvy = wsum(mvy);
    if (lane == 0) dst[i] = make_float2(pi.x - mvx, pi.y - mvy);
}

extern "C" void kernel_launch(void* const* d_in, const int* in_sizes, int n_in,
                              void* d_out, int out_size) {
    const float* pos = (const float*)d_in[0];
    const float* ori = (const float*)d_in[1];
    const float* del = (const float*)d_in[2];
    const float* rno = (const float*)d_in[3];
    const float* tno = (const float*)d_in[4];
    float* out = (float*)d_out;
    const int n = in_sizes[3];   // rot_noise has N elements

    const int threads = 256;
    const int blocks = (n * 32 + threads - 1) / threads;   // one warp per particle

    pack_kernel<<<(n + 255) / 256, 256>>>((const float2*)pos, (const float2*)ori, n);
    mean_kernel<<<1, 1024>>>(pos, n);
    main_kernel<<<blocks, threads>>>(pos, ori, del, rno, tno, out, n);
    collide_kernel<<<blocks, threads>>>(0, nullptr, n);
    collide_kernel<<<blocks, threads>>>(1, nullptr, n);
    collide_kernel<<<blocks, threads>>>(2, (float2*)out, n);
}